// round 15
// baseline (speedup 1.0000x reference)
#include <cuda_runtime.h>
#include <cstdint>

#define Fq   20
#define Dq   16
#define NBq  500000
#define Bq   4096
#define NIq  190          // F*(F-1)/2
#define NJP  192          // NIq padded
#define FDq  320          // F*D

// Device-global scratch
__device__ __align__(16) float g_W12[FDq * NJP];   // w1@w2, [k][j] padded
__device__ __align__(16) float g_W[Bq * NIq];      // z@w1@w2 : [b][j]
__device__ int g_done;                             // w12 tiles completed

#define W12B      240                       // 20 x 12 tiles of 16x16
#define SN_TB     16
#define SN_ZS     20
#define SN_KC     32
#define SN_BLOCKS (Bq / SN_TB)              // 256

// packed fp32x2 FMA (element-wise, exact fp32 rounding)
union F2U { float2 f; unsigned long long u; };
__device__ __forceinline__ float2 ffma2(float2 a, float2 b, float2 c) {
    F2U A, B, C; A.f = a; B.f = b; C.f = c;
    asm("fma.rn.f32x2 %0, %1, %2, %0;" : "+l"(C.u) : "l"(A.u), "l"(B.u));
    return C.f;
}

// ---------------------------------------------------------------------------
// K1 (fused, grid-split, 256 threads):
//   bids [0,240):    w12f GEMM tiles -> g_W12, signal g_done
//   bids [240,496):  SeNet (spins on g_done==240; whole grid fits in wave 1,
//                    and all w12 producers are resident -> no deadlock)
// ---------------------------------------------------------------------------
__global__ __launch_bounds__(256) void k_ws(
    const float* __restrict__ w1,        // (320,320)
    const float* __restrict__ w2,        // (320,190)
    const float* __restrict__ z)         // (B, 320)
{
    __shared__ union {
        struct { float As[16][65]; float Bs[64][17]; } w12;             // 8.5 KB
        struct { float zsT[FDq * SN_ZS]; float wsm[SN_KC * NJP]; } sen; // 50.2 KB
    } sm;

    const int tid = threadIdx.x;
    const int bid = blockIdx.x;

    if (bid < W12B) {
        // ================= w12f: 16x16 tile, k-chunk 64 =================
        auto& As = sm.w12.As;
        auto& Bs = sm.w12.Bs;
        const int ti = bid / 12, tj = bid % 12;
        const int row0 = ti * 16, col0 = tj * 16;
        const int r = tid >> 4, j = tid & 15;
        float acc = 0.f;
        for (int kc = 0; kc < FDq; kc += 64) {
            #pragma unroll
            for (int q = 0; q < 4; q++) {
                int idx = tid + 256 * q;
                int rr = idx >> 6, kk = idx & 63;
                As[rr][kk] = w1[(row0 + rr) * FDq + kc + kk];
            }
            #pragma unroll
            for (int q = 0; q < 4; q++) {
                int idx = tid + 256 * q;
                int kk = idx >> 4, cc = idx & 15;
                int col = col0 + cc;
                Bs[kk][cc] = (col < NIq) ? w2[(kc + kk) * NIq + col] : 0.f;
            }
            __syncthreads();
            #pragma unroll
            for (int k = 0; k < 64; k++)
                acc += As[r][k] * Bs[k][j];
            __syncthreads();
        }
        g_W12[(row0 + r) * NJP + col0 + j] = acc;
        __threadfence();
        __syncthreads();
        if (tid == 0) atomicAdd(&g_done, 1);
    } else {
        // ================= SeNet (waits on g_done) =================
        float* zsT = sm.sen.zsT;
        float* wsm = sm.sen.wsm;
        const int b0 = (bid - W12B) * SN_TB;

        {   // stage z transposed: [k][b] (independent of w12)
            const float4* src = (const float4*)(z + b0 * FDq);
            for (int i = tid; i < SN_TB * FDq / 4; i += 256) {
                float4 v = src[i];
                int e = i * 4;
                int b = e / FDq;
                int k = e - b * FDq;
                zsT[ k      * SN_ZS + b] = v.x;
                zsT[(k + 1) * SN_ZS + b] = v.y;
                zsT[(k + 2) * SN_ZS + b] = v.z;
                zsT[(k + 3) * SN_ZS + b] = v.w;
            }
        }

        if (tid == 0) {
            while (atomicAdd(&g_done, 0) < W12B) __nanosleep(64);
        }
        // first __syncthreads in the kc loop releases everyone after the spin

        const int bg = tid & 3;
        const int jg = tid >> 2;       // 0..63; only 0..47 compute
        float2 acc[4][2];
        #pragma unroll
        for (int jj = 0; jj < 4; jj++) {
            acc[jj][0] = make_float2(0.f, 0.f);
            acc[jj][1] = make_float2(0.f, 0.f);
        }

        for (int kc = 0; kc < FDq; kc += SN_KC) {
            __syncthreads();                   // covers z-stage + spin on iter 0
            const float4* wsrc = (const float4*)(g_W12 + kc * NJP);
            for (int i = tid; i < SN_KC * NJP / 4; i += 256)
                ((float4*)wsm)[i] = wsrc[i];
            __syncthreads();
            if (jg < 48) {
                #pragma unroll 4
                for (int k = 0; k < SN_KC; k++) {
                    float4 w4 = *(const float4*)(wsm + k * NJP + jg * 4);
                    float4 z4 = *(const float4*)(zsT + (kc + k) * SN_ZS + bg * 4);
                    float2 z01 = make_float2(z4.x, z4.y);
                    float2 z23 = make_float2(z4.z, z4.w);
                    acc[0][0] = ffma2(z01, make_float2(w4.x, w4.x), acc[0][0]);
                    acc[0][1] = ffma2(z23, make_float2(w4.x, w4.x), acc[0][1]);
                    acc[1][0] = ffma2(z01, make_float2(w4.y, w4.y), acc[1][0]);
                    acc[1][1] = ffma2(z23, make_float2(w4.y, w4.y), acc[1][1]);
                    acc[2][0] = ffma2(z01, make_float2(w4.z, w4.z), acc[2][0]);
                    acc[2][1] = ffma2(z23, make_float2(w4.z, w4.z), acc[2][1]);
                    acc[3][0] = ffma2(z01, make_float2(w4.w, w4.w), acc[3][0]);
                    acc[3][1] = ffma2(z23, make_float2(w4.w, w4.w), acc[3][1]);
                }
            }
        }
        if (jg < 48) {
            #pragma unroll
            for (int jj = 0; jj < 4; jj++) {
                int j = jg * 4 + jj;
                if (j < NIq) {
                    int b = b0 + bg * 4;
                    g_W[ b      * NIq + j] = acc[jj][0].x;
                    g_W[(b + 1) * NIq + j] = acc[jj][0].y;
                    g_W[(b + 2) * NIq + j] = acc[jj][1].x;
                    g_W[(b + 3) * NIq + j] = acc[jj][1].y;
                }
            }
        }
    }
}

// ---------------------------------------------------------------------------
// K2: combine — NO precomputed tables. Per block (2 batches):
//  P1: per (bb,j,tbl): gather raw codebook row (4x LDG.128, L2-resident),
//      scale by w[b,j], store 16 floats to u[bb][j][tbl*16..].
//  P2: per (bb,f,c): sum 19 float4 rows -> vs[bb][f][c*4..].
//  P3: per (bb,f,d): 32-FMA transform with W column d in registers.
// ---------------------------------------------------------------------------
#define BPB 2
#define UST 36                        // u row stride (floats); 32 data + pad
__global__ __launch_bounds__(256) void k_combine(
    const float* __restrict__ codebook,  // (500000,16)
    const float* __restrict__ Wt,        // (32,16)
    const int*   __restrict__ hash_idx,  // (2, B, NI)
    const int*   __restrict__ inter,     // (20, 19)
    float*       __restrict__ out)       // (B, 20, 16)
{
    __shared__ float ws[BPB * NIq];
    __shared__ int   hs[2][BPB * NIq];
    __shared__ int   idxs[Fq * (Fq - 1)];
    __shared__ float Wsm[512];
    __shared__ __align__(16) float u[BPB][NIq * UST];   // 54.7 KB
    __shared__ __align__(16) float vs[BPB][Fq * 36];    // 5.8 KB

    const int b0  = blockIdx.x * BPB;
    const int tid = threadIdx.x;

    for (int i = tid; i < BPB * NIq; i += 256) {
        int bb = i / NIq, j = i - bb * NIq;
        ws[i]    = g_W[(b0 + bb) * NIq + j];
        hs[0][i] = hash_idx[(b0 + bb) * NIq + j];
        hs[1][i] = hash_idx[Bq * NIq + (b0 + bb) * NIq + j];
    }
    for (int i = tid; i < Fq * (Fq - 1); i += 256) idxs[i] = inter[i];
    for (int i = tid; i < 512; i += 256) Wsm[i] = Wt[i];
    __syncthreads();

    // ---- phase 1: 760 items = (bb, j, tbl), 4 gathers in flight each ----
    const float4* cb4 = (const float4*)codebook;
    #pragma unroll
    for (int s = 0; s < 3; s++) {
        int t = tid + s * 256;
        if (t < BPB * NIq * 2) {
            int bb  = t / (NIq * 2);
            int rem = t - bb * (NIq * 2);
            int j = rem >> 1, tbl = rem & 1;
            int ii = bb * NIq + j;
            int idx = hs[tbl][ii];
            float w = ws[ii];
            float4 g0 = cb4[idx * 4 + 0];
            float4 g1 = cb4[idx * 4 + 1];
            float4 g2 = cb4[idx * 4 + 2];
            float4 g3 = cb4[idx * 4 + 3];
            float4* dst = (float4*)(&u[bb][j * UST + tbl * 16]);
            dst[0] = make_float4(g0.x * w, g0.y * w, g0.z * w, g0.w * w);
            dst[1] = make_float4(g1.x * w, g1.y * w, g1.z * w, g1.w * w);
            dst[2] = make_float4(g2.x * w, g2.y * w, g2.z * w, g2.w * w);
            dst[3] = make_float4(g3.x * w, g3.y * w, g3.z * w, g3.w * w);
        }
    }
    __syncthreads();

    // ---- phase 2: 320 items = (bb, f, c), c = float4 slot in 32 floats ----
    for (int t = tid; t < BPB * Fq * 8; t += 256) {
        int c  = t & 7;
        int f  = (t >> 3) % Fq;
        int bb = t / (Fq * 8);
        const int* row = idxs + f * (Fq - 1);
        float4 s = make_float4(0.f, 0.f, 0.f, 0.f);
        #pragma unroll
        for (int p = 0; p < Fq - 1; p++) {
            float4 v = *(const float4*)(&u[bb][row[p] * UST + c * 4]);
            s.x += v.x; s.y += v.y; s.z += v.z; s.w += v.w;
        }
        *(float4*)(&vs[bb][f * 36 + c * 4]) = s;
    }
    __syncthreads();

    // ---- phase 3: out[b,f,d] = sum_k vs[b][f][k] * W[k][d] ----
    {
        const int d = tid & 15;
        float wcol[32];
        #pragma unroll
        for (int k = 0; k < 32; k++) wcol[k] = Wsm[k * 16 + d];
        for (int o = tid >> 4; o < BPB * Fq; o += 16) {
            int bb = o / Fq, f = o - bb * Fq;
            const float* v = &vs[bb][f * 36];
            float s = 0.f;
            #pragma unroll
            for (int k = 0; k < 32; k++) s += v[k] * wcol[k];
            out[(b0 + bb) * Fq * Dq + f * Dq + d] = s;
        }
    }
}

// ---------------------------------------------------------------------------
extern "C" void kernel_launch(void* const* d_in, const int* in_sizes, int n_in,
                              void* d_out, int out_size) {
    const float* origin   = (const float*)d_in[0];  // (B, F, D)
    const float* codebook = (const float*)d_in[1];  // (NB, D)
    const float* Wt       = (const float*)d_in[2];  // (32, 16)
    const float* w1       = (const float*)d_in[3];  // (320, 320)
    const float* w2       = (const float*)d_in[4];  // (320, 190)
    const int*   hash     = (const int*)d_in[5];    // (2, B, NI)
    const int*   inter    = (const int*)d_in[6];    // (20, 19)
    float*       out      = (float*)d_out;

    // reset the w12 completion counter (graph-legal memset node)
    void* daddr = nullptr;
    cudaGetSymbolAddress(&daddr, g_done);
    cudaMemsetAsync(daddr, 0, sizeof(int), 0);

    k_ws<<<W12B + SN_BLOCKS, 256>>>(w1, w2, origin);
    k_combine<<<Bq / BPB, 256>>>(codebook, Wt, hash, inter, out);
}

// round 16
// speedup vs baseline: 1.2002x; 1.2002x over previous
#include <cuda_runtime.h>
#include <cuda_fp16.h>
#include <cstdint>

#define Fq   20
#define Dq   16
#define NBq  500000
#define Bq   4096
#define NIq  190          // F*(F-1)/2
#define NJP  192          // NIq padded
#define FDq  320          // F*D

// Device-global scratch
__device__ __align__(16) float  g_W12[FDq * NJP];   // w1@w2, [k][j] padded
__device__ __align__(16) float  g_W[Bq * NIq];      // z@w1@w2 : [b][j]
__device__ __align__(16) __half g_CT0h[NBq * Dq];   // codebook @ W_top : 16 MB
__device__ __align__(16) __half g_CT1h[NBq * Dq];   // codebook @ W_bot : 16 MB

#define W12_TILES 60                        // 10 x 6 tiles of 32x32
#define CT_TILE   256                       // rows per pipeline stage
#define CT_NTILE  2                         // stages per block (512 rows)
#define CT_RPB    (CT_TILE * CT_NTILE)
#define CT_BLOCKS ((NBq + CT_RPB - 1) / CT_RPB)   // 977

// packed fp32x2 FMA (element-wise, exact fp32 rounding)
union F2U { float2 f; unsigned long long u; };
__device__ __forceinline__ float2 ffma2(float2 a, float2 b, float2 c) {
    F2U A, B, C; A.f = a; B.f = b; C.f = c;
    asm("fma.rn.f32x2 %0, %1, %2, %0;" : "+l"(C.u) : "l"(A.u), "l"(B.u));
    return C.f;
}

__device__ __forceinline__ void cp16(uint32_t s, const void* g) {
    asm volatile("cp.async.cg.shared.global [%0], [%1], 16;" :: "r"(s), "l"(g));
}
__device__ __forceinline__ void cp_commit() {
    asm volatile("cp.async.commit_group;");
}
template <int N> __device__ __forceinline__ void cp_wait() {
    asm volatile("cp.async.wait_group %0;" :: "n"(N));
}

// ---------------------------------------------------------------------------
// K1 (fused, grid-split, 256 threads) — identical to the 68.3 best:
//   blocks [0,60):  tiled GEMM  g_W12 = w1 @ w2   (hidden under the CT wave)
//   blocks [60,..): codebook transform -> fp16 CT0/CT1.
// ---------------------------------------------------------------------------
__global__ __launch_bounds__(256) void k_pre(
    const float* __restrict__ w1,        // (320,320)
    const float* __restrict__ w2,        // (320,190)
    const float* __restrict__ Wt,        // (32,16)
    const float* __restrict__ codebook)  // (500000,16)
{
    __shared__ union {
        struct { float As[32][33]; float Bs[32][33]; } gemm;   // 8.4 KB
        float csm[2][CT_TILE * 16];                            // 32 KB
    } sm;

    const int tid = threadIdx.x;

    if (blockIdx.x < W12_TILES) {
        auto& As = sm.gemm.As;
        auto& Bs = sm.gemm.Bs;
        const int tile = blockIdx.x;
        const int ti = tile / 6, tj = tile % 6;
        const int row0 = ti * 32, col0 = tj * 32;
        const int tx = tid & 15, ty = tid >> 4;
        float a00 = 0.f, a01 = 0.f, a10 = 0.f, a11 = 0.f;
        for (int k0 = 0; k0 < FDq; k0 += 32) {
            #pragma unroll
            for (int i = tid; i < 32 * 32; i += 256) {
                int r = i >> 5, c = i & 31;
                As[r][c] = w1[(row0 + r) * FDq + k0 + c];
                int cb = col0 + c;
                Bs[r][c] = (cb < NIq) ? w2[(k0 + r) * NIq + cb] : 0.f;
            }
            __syncthreads();
            #pragma unroll
            for (int k = 0; k < 32; k++) {
                float x0 = As[ty * 2][k],  x1 = As[ty * 2 + 1][k];
                float y0 = Bs[k][tx * 2],  y1 = Bs[k][tx * 2 + 1];
                a00 += x0 * y0; a01 += x0 * y1;
                a10 += x1 * y0; a11 += x1 * y1;
            }
            __syncthreads();
        }
        int i0 = row0 + ty * 2, j0 = col0 + tx * 2;
        g_W12[ i0      * NJP + j0    ] = a00;
        g_W12[ i0      * NJP + j0 + 1] = a01;
        g_W12[(i0 + 1) * NJP + j0    ] = a10;
        g_W12[(i0 + 1) * NJP + j0 + 1] = a11;
    } else {
        const int dg  = tid & 15;       // d-group: 2 output cols
        const int rs  = tid >> 4;       // row slot 0..15
        const int tbl = dg >> 3;        // 0 -> CT0, 1 -> CT1
        const int dd  = (dg & 7) * 2;   // output cols dd, dd+1

        float2 wA[8], wB[8];
        #pragma unroll
        for (int m = 0; m < 8; m++) {
            const float* wr0 = Wt + (tbl * 16 + 2 * m)     * 16;
            const float* wr1 = Wt + (tbl * 16 + 2 * m + 1) * 16;
            wA[m] = make_float2(wr0[dd],     wr1[dd]);
            wB[m] = make_float2(wr0[dd + 1], wr1[dd + 1]);
        }

        __half* ct = tbl ? g_CT1h : g_CT0h;
        const long base = (long)(blockIdx.x - W12_TILES) * CT_RPB;
        const float4* cb4 = (const float4*)codebook;

        auto stage = [&](int t, int buf) {
            #pragma unroll
            for (int q = 0; q < 4; q++) {
                int  i = q * 256 + tid;                  // float4 idx in tile
                long r = base + (long)t * CT_TILE + (i >> 2);
                long ri = (r < NBq) ? r : (NBq - 1);
                uint32_t s = (uint32_t)__cvta_generic_to_shared(&sm.csm[buf][i * 4]);
                cp16(s, &cb4[ri * 4 + (i & 3)]);
            }
            cp_commit();
        };

        stage(0, 0);
        for (int t = 0; t < CT_NTILE; t++) {
            if (t + 1 < CT_NTILE) { stage(t + 1, (t + 1) & 1); cp_wait<1>(); }
            else                  { cp_wait<0>(); }
            __syncthreads();
            const float* buf = sm.csm[t & 1];
            const long tile0 = base + (long)t * CT_TILE;
            #pragma unroll
            for (int rr = 0; rr < 16; rr++) {
                int  lr = rs + rr * 16;
                long r  = tile0 + lr;
                if (r >= NBq) continue;
                const float4* cp4 = (const float4*)(buf + lr * 16);
                float2 sA = make_float2(0.f, 0.f);
                float2 sB = make_float2(0.f, 0.f);
                #pragma unroll
                for (int m = 0; m < 4; m++) {
                    float4 v = cp4[m];                   // LDS.128 broadcast
                    float2 c01 = make_float2(v.x, v.y);
                    float2 c23 = make_float2(v.z, v.w);
                    sA = ffma2(c01, wA[2 * m],     sA);
                    sB = ffma2(c01, wB[2 * m],     sB);
                    sA = ffma2(c23, wA[2 * m + 1], sA);
                    sB = ffma2(c23, wB[2 * m + 1], sB);
                }
                *(__half2*)(ct + r * Dq + dd) =
                    __floats2half2_rn(sA.x + sA.y, sB.x + sB.y);
            }
            __syncthreads();
        }
    }
}

// ---------------------------------------------------------------------------
// K2: g_W = Z @ W12.  RE-TILED: 128 blocks x 32 batches x 192 cols.
// Thread = 8 cols x 4 batches: per k, 3 LDS.128 feed 16 FFMA2 (was 2:8).
// ---------------------------------------------------------------------------
#define SN_TB 32
#define SN_ZS 36                 // padded batch stride (32 + 4)
#define SN_NT 192
#define SN_KC 32
__global__ __launch_bounds__(SN_NT) void k_senet(const float* __restrict__ z) {
    __shared__ __align__(16) float zsT[FDq * SN_ZS];     // [k][b pad 36] 46.1 KB
    __shared__ __align__(16) float wsm[SN_KC * NJP];     // 24.6 KB
    const int b0  = blockIdx.x * SN_TB;
    const int tid = threadIdx.x;

    {   // stage z transposed: [k][b]
        const float4* src = (const float4*)(z + b0 * FDq);
        for (int i = tid; i < SN_TB * FDq / 4; i += SN_NT) {
            float4 v = src[i];
            int e = i * 4;
            int b = e / FDq;
            int k = e - b * FDq;
            zsT[ k      * SN_ZS + b] = v.x;
            zsT[(k + 1) * SN_ZS + b] = v.y;
            zsT[(k + 2) * SN_ZS + b] = v.z;
            zsT[(k + 3) * SN_ZS + b] = v.w;
        }
    }

    const int bg = tid & 7;        // batch quad 0..7  (batches bg*4 .. bg*4+3)
    const int jg = tid >> 3;       // col octet 0..23  (cols jg*8 .. jg*8+7)
    float2 acc[8][2];              // [col][batch-pair]
    #pragma unroll
    for (int jj = 0; jj < 8; jj++) {
        acc[jj][0] = make_float2(0.f, 0.f);
        acc[jj][1] = make_float2(0.f, 0.f);
    }

    for (int kc = 0; kc < FDq; kc += SN_KC) {
        __syncthreads();                       // covers zsT on first iter
        const float4* wsrc = (const float4*)(g_W12 + kc * NJP);
        for (int i = tid; i < SN_KC * NJP / 4; i += SN_NT)
            ((float4*)wsm)[i] = wsrc[i];
        __syncthreads();
        #pragma unroll 2
        for (int k = 0; k < SN_KC; k++) {
            const float4* wp = (const float4*)(wsm + k * NJP + jg * 8);
            float4 wa = wp[0];                                         // LDS.128
            float4 wb = wp[1];                                         // LDS.128
            float4 z4 = *(const float4*)(zsT + (kc + k) * SN_ZS + bg * 4); // LDS.128
            float2 z01 = make_float2(z4.x, z4.y);
            float2 z23 = make_float2(z4.z, z4.w);
            acc[0][0] = ffma2(z01, make_float2(wa.x, wa.x), acc[0][0]);
            acc[0][1] = ffma2(z23, make_float2(wa.x, wa.x), acc[0][1]);
            acc[1][0] = ffma2(z01, make_float2(wa.y, wa.y), acc[1][0]);
            acc[1][1] = ffma2(z23, make_float2(wa.y, wa.y), acc[1][1]);
            acc[2][0] = ffma2(z01, make_float2(wa.z, wa.z), acc[2][0]);
            acc[2][1] = ffma2(z23, make_float2(wa.z, wa.z), acc[2][1]);
            acc[3][0] = ffma2(z01, make_float2(wa.w, wa.w), acc[3][0]);
            acc[3][1] = ffma2(z23, make_float2(wa.w, wa.w), acc[3][1]);
            acc[4][0] = ffma2(z01, make_float2(wb.x, wb.x), acc[4][0]);
            acc[4][1] = ffma2(z23, make_float2(wb.x, wb.x), acc[4][1]);
            acc[5][0] = ffma2(z01, make_float2(wb.y, wb.y), acc[5][0]);
            acc[5][1] = ffma2(z23, make_float2(wb.y, wb.y), acc[5][1]);
            acc[6][0] = ffma2(z01, make_float2(wb.z, wb.z), acc[6][0]);
            acc[6][1] = ffma2(z23, make_float2(wb.z, wb.z), acc[6][1]);
            acc[7][0] = ffma2(z01, make_float2(wb.w, wb.w), acc[7][0]);
            acc[7][1] = ffma2(z23, make_float2(wb.w, wb.w), acc[7][1]);
        }
    }
    #pragma unroll
    for (int jj = 0; jj < 8; jj++) {
        int j = jg * 8 + jj;
        if (j < NIq) {
            int b = b0 + bg * 4;
            g_W[ b      * NIq + j] = acc[jj][0].x;
            g_W[(b + 1) * NIq + j] = acc[jj][0].y;
            g_W[(b + 2) * NIq + j] = acc[jj][1].x;
            g_W[(b + 3) * NIq + j] = acc[jj][1].y;
        }
    }
}

// ---------------------------------------------------------------------------
// K3: combine — identical to the 68.3 best (MLP-6 fp16 gathers, scalar P2).
// ---------------------------------------------------------------------------
#define BPB 2
#define P1_ITEMS (BPB * NIq * 2)     // 760
__global__ __launch_bounds__(256) void k_combine(
    const int* __restrict__ hash_idx,    // (2, B, NI)
    const int* __restrict__ inter,       // (20, 19)
    float*     __restrict__ out)         // (B, 20, 16)
{
    __shared__ float ws[BPB * NIq];
    __shared__ __align__(16) float embw[BPB][NIq * 20];
    __shared__ int idxs[Fq * (Fq - 1)];
    __shared__ int hs0[BPB * NIq];
    __shared__ int hs1[BPB * NIq];

    const int b0  = blockIdx.x * BPB;
    const int tid = threadIdx.x;

    for (int i = tid; i < BPB * NIq; i += 256) {
        int bb = i / NIq, j = i - bb * NIq;
        ws[i]  = g_W[(b0 + bb) * NIq + j];
        hs0[i] = hash_idx[(b0 + bb) * NIq + j];
        hs1[i] = hash_idx[Bq * NIq + (b0 + bb) * NIq + j];
    }
    for (int i = tid; i < Fq * (Fq - 1); i += 256) idxs[i] = inter[i];
    __syncthreads();

    uint4 av[3], cv[3];
    float wv[3];
    int jjv[3], qv[3];
    bool val[3];
    #pragma unroll
    for (int s = 0; s < 3; s++) {
        int t = tid + s * 256;
        val[s] = (t < P1_ITEMS);
        if (val[s]) {
            int jj = t >> 1, q = t & 1;
            jjv[s] = jj; qv[s] = q;
            av[s] = *(const uint4*)(g_CT0h + hs0[jj] * Dq + q * 8);
            cv[s] = *(const uint4*)(g_CT1h + hs1[jj] * Dq + q * 8);
            wv[s] = ws[jj];
        }
    }
    #pragma unroll
    for (int s = 0; s < 3; s++) {
        if (!val[s]) continue;
        float w = wv[s];
        float2 fa, fc;
        float o[8];
        fa = __half22float2(*(__half2*)&av[s].x); fc = __half22float2(*(__half2*)&cv[s].x);
        o[0] = (fa.x + fc.x) * w; o[1] = (fa.y + fc.y) * w;
        fa = __half22float2(*(__half2*)&av[s].y); fc = __half22float2(*(__half2*)&cv[s].y);
        o[2] = (fa.x + fc.x) * w; o[3] = (fa.y + fc.y) * w;
        fa = __half22float2(*(__half2*)&av[s].z); fc = __half22float2(*(__half2*)&cv[s].z);
        o[4] = (fa.x + fc.x) * w; o[5] = (fa.y + fc.y) * w;
        fa = __half22float2(*(__half2*)&av[s].w); fc = __half22float2(*(__half2*)&cv[s].w);
        o[6] = (fa.x + fc.x) * w; o[7] = (fa.y + fc.y) * w;
        int bb = jjv[s] / NIq, j = jjv[s] - bb * NIq;
        float* dst = &embw[bb][j * 20 + qv[s] * 8];
        *(float4*)dst       = make_float4(o[0], o[1], o[2], o[3]);
        *(float4*)(dst + 4) = make_float4(o[4], o[5], o[6], o[7]);
    }
    __syncthreads();

    #pragma unroll 2
    for (int o = tid; o < BPB * Fq * Dq; o += 256) {
        int bb = o / (Fq * Dq);
        int oo = o - bb * (Fq * Dq);
        int f = oo >> 4, d = oo & 15;
        const int* row = idxs + f * (Fq - 1);
        float s = 0.f;
        #pragma unroll
        for (int p = 0; p < Fq - 1; p++)
            s += embw[bb][row[p] * 20 + d];
        out[(b0 + bb) * Fq * Dq + oo] = s;
    }
}

// ---------------------------------------------------------------------------
extern "C" void kernel_launch(void* const* d_in, const int* in_sizes, int n_in,
                              void* d_out, int out_size) {
    const float* origin   = (const float*)d_in[0];  // (B, F, D)
    const float* codebook = (const float*)d_in[1];  // (NB, D)
    const float* Wt       = (const float*)d_in[2];  // (32, 16)
    const float* w1       = (const float*)d_in[3];  // (320, 320)
    const float* w2       = (const float*)d_in[4];  // (320, 190)
    const int*   hash     = (const int*)d_in[5];    // (2, B, NI)
    const int*   inter    = (const int*)d_in[6];    // (20, 19)
    float*       out      = (float*)d_out;

    k_pre<<<W12_TILES + CT_BLOCKS, 256>>>(w1, w2, Wt, codebook);
    k_senet<<<Bq / SN_TB, SN_NT>>>(origin);
    k_combine<<<Bq / BPB, 256>>>(hash, inter, out);
}

// round 17
// speedup vs baseline: 1.3697x; 1.1413x over previous
#include <cuda_runtime.h>
#include <cuda_fp16.h>
#include <cstdint>

#define Fq   20
#define Dq   16
#define NBq  500000
#define Bq   4096
#define NIq  190          // F*(F-1)/2
#define NJP  192          // NIq padded
#define FDq  320          // F*D

// Device-global scratch
__device__ __align__(16) float  g_W12[FDq * NJP];   // w1@w2, [k][j] padded
__device__ __align__(16) float  g_W[Bq * NIq];      // z@w1@w2 : [b][j]
__device__ __align__(16) __half g_CT0h[NBq * Dq];   // codebook @ W_top : 16 MB
__device__ __align__(16) __half g_CT1h[NBq * Dq];   // codebook @ W_bot : 16 MB

#define W12_TILES 60                        // 10 x 6 tiles of 32x32
#define CT_TILE   256                       // rows per pipeline stage
#define CT_NTILE  2                         // stages per block (512 rows)
#define CT_RPB    (CT_TILE * CT_NTILE)
#define CT_BLOCKS ((NBq + CT_RPB - 1) / CT_RPB)   // 977

// packed fp32x2 FMA (element-wise, exact fp32 rounding)
union F2U { float2 f; unsigned long long u; };
__device__ __forceinline__ float2 ffma2(float2 a, float2 b, float2 c) {
    F2U A, B, C; A.f = a; B.f = b; C.f = c;
    asm("fma.rn.f32x2 %0, %1, %2, %0;" : "+l"(C.u) : "l"(A.u), "l"(B.u));
    return C.f;
}

__device__ __forceinline__ void cp16(uint32_t s, const void* g) {
    asm volatile("cp.async.cg.shared.global [%0], [%1], 16;" :: "r"(s), "l"(g));
}
__device__ __forceinline__ void cp_commit() {
    asm volatile("cp.async.commit_group;");
}
template <int N> __device__ __forceinline__ void cp_wait() {
    asm volatile("cp.async.wait_group %0;" :: "n"(N));
}

// ---------------------------------------------------------------------------
// K1 (fused, grid-split, 256 threads) — identical to the 68.3 best:
//   blocks [0,60):  tiled GEMM  g_W12 = w1 @ w2   (hidden under the CT wave)
//   blocks [60,..): codebook transform -> fp16 CT0/CT1.
// ---------------------------------------------------------------------------
__global__ __launch_bounds__(256) void k_pre(
    const float* __restrict__ w1,        // (320,320)
    const float* __restrict__ w2,        // (320,190)
    const float* __restrict__ Wt,        // (32,16)
    const float* __restrict__ codebook)  // (500000,16)
{
    __shared__ union {
        struct { float As[32][33]; float Bs[32][33]; } gemm;   // 8.4 KB
        float csm[2][CT_TILE * 16];                            // 32 KB
    } sm;

    const int tid = threadIdx.x;

    if (blockIdx.x < W12_TILES) {
        auto& As = sm.gemm.As;
        auto& Bs = sm.gemm.Bs;
        const int tile = blockIdx.x;
        const int ti = tile / 6, tj = tile % 6;
        const int row0 = ti * 32, col0 = tj * 32;
        const int tx = tid & 15, ty = tid >> 4;
        float a00 = 0.f, a01 = 0.f, a10 = 0.f, a11 = 0.f;
        for (int k0 = 0; k0 < FDq; k0 += 32) {
            #pragma unroll
            for (int i = tid; i < 32 * 32; i += 256) {
                int r = i >> 5, c = i & 31;
                As[r][c] = w1[(row0 + r) * FDq + k0 + c];
                int cb = col0 + c;
                Bs[r][c] = (cb < NIq) ? w2[(k0 + r) * NIq + cb] : 0.f;
            }
            __syncthreads();
            #pragma unroll
            for (int k = 0; k < 32; k++) {
                float x0 = As[ty * 2][k],  x1 = As[ty * 2 + 1][k];
                float y0 = Bs[k][tx * 2],  y1 = Bs[k][tx * 2 + 1];
                a00 += x0 * y0; a01 += x0 * y1;
                a10 += x1 * y0; a11 += x1 * y1;
            }
            __syncthreads();
        }
        int i0 = row0 + ty * 2, j0 = col0 + tx * 2;
        g_W12[ i0      * NJP + j0    ] = a00;
        g_W12[ i0      * NJP + j0 + 1] = a01;
        g_W12[(i0 + 1) * NJP + j0    ] = a10;
        g_W12[(i0 + 1) * NJP + j0 + 1] = a11;
    } else {
        const int dg  = tid & 15;       // d-group: 2 output cols
        const int rs  = tid >> 4;       // row slot 0..15
        const int tbl = dg >> 3;        // 0 -> CT0, 1 -> CT1
        const int dd  = (dg & 7) * 2;   // output cols dd, dd+1

        float2 wA[8], wB[8];
        #pragma unroll
        for (int m = 0; m < 8; m++) {
            const float* wr0 = Wt + (tbl * 16 + 2 * m)     * 16;
            const float* wr1 = Wt + (tbl * 16 + 2 * m + 1) * 16;
            wA[m] = make_float2(wr0[dd],     wr1[dd]);
            wB[m] = make_float2(wr0[dd + 1], wr1[dd + 1]);
        }

        __half* ct = tbl ? g_CT1h : g_CT0h;
        const long base = (long)(blockIdx.x - W12_TILES) * CT_RPB;
        const float4* cb4 = (const float4*)codebook;

        auto stage = [&](int t, int buf) {
            #pragma unroll
            for (int q = 0; q < 4; q++) {
                int  i = q * 256 + tid;                  // float4 idx in tile
                long r = base + (long)t * CT_TILE + (i >> 2);
                long ri = (r < NBq) ? r : (NBq - 1);
                uint32_t s = (uint32_t)__cvta_generic_to_shared(&sm.csm[buf][i * 4]);
                cp16(s, &cb4[ri * 4 + (i & 3)]);
            }
            cp_commit();
        };

        stage(0, 0);
        for (int t = 0; t < CT_NTILE; t++) {
            if (t + 1 < CT_NTILE) { stage(t + 1, (t + 1) & 1); cp_wait<1>(); }
            else                  { cp_wait<0>(); }
            __syncthreads();
            const float* buf = sm.csm[t & 1];
            const long tile0 = base + (long)t * CT_TILE;
            #pragma unroll
            for (int rr = 0; rr < 16; rr++) {
                int  lr = rs + rr * 16;
                long r  = tile0 + lr;
                if (r >= NBq) continue;
                const float4* cp4 = (const float4*)(buf + lr * 16);
                float2 sA = make_float2(0.f, 0.f);
                float2 sB = make_float2(0.f, 0.f);
                #pragma unroll
                for (int m = 0; m < 4; m++) {
                    float4 v = cp4[m];                   // LDS.128 broadcast
                    float2 c01 = make_float2(v.x, v.y);
                    float2 c23 = make_float2(v.z, v.w);
                    sA = ffma2(c01, wA[2 * m],     sA);
                    sB = ffma2(c01, wB[2 * m],     sB);
                    sA = ffma2(c23, wA[2 * m + 1], sA);
                    sB = ffma2(c23, wB[2 * m + 1], sB);
                }
                *(__half2*)(ct + r * Dq + dd) =
                    __floats2half2_rn(sA.x + sA.y, sB.x + sB.y);
            }
            __syncthreads();
        }
    }
}

// ---------------------------------------------------------------------------
// K2: g_W = Z @ W12.  256 blocks x 16 batches x 192 cols — identical to the
// 68.3 best (thread = 4 cols x 4 batches, zsT stride 20).
// ---------------------------------------------------------------------------
#define SN_TB 16
#define SN_ZS 20                 // padded batch stride
#define SN_NT 192
#define SN_KC 32
__global__ __launch_bounds__(SN_NT) void k_senet(const float* __restrict__ z) {
    __shared__ __align__(16) float zsT[FDq * SN_ZS];     // [k][b pad 20]
    __shared__ __align__(16) float wsm[SN_KC * NJP];
    const int b0  = blockIdx.x * SN_TB;
    const int tid = threadIdx.x;

    {   // stage z transposed: [k][b]
        const float4* src = (const float4*)(z + b0 * FDq);
        for (int i = tid; i < SN_TB * FDq / 4; i += SN_NT) {
            float4 v = src[i];
            int e = i * 4;
            int b = e / FDq;
            int k = e - b * FDq;
            zsT[ k      * SN_ZS + b] = v.x;
            zsT[(k + 1) * SN_ZS + b] = v.y;
            zsT[(k + 2) * SN_ZS + b] = v.z;
            zsT[(k + 3) * SN_ZS + b] = v.w;
        }
    }

    const int bg = tid & 3;
    const int jg = tid >> 2;
    float2 acc[4][2];
    #pragma unroll
    for (int jj = 0; jj < 4; jj++) {
        acc[jj][0] = make_float2(0.f, 0.f);
        acc[jj][1] = make_float2(0.f, 0.f);
    }

    for (int kc = 0; kc < FDq; kc += SN_KC) {
        __syncthreads();
        const float4* wsrc = (const float4*)(g_W12 + kc * NJP);
        for (int i = tid; i < SN_KC * NJP / 4; i += SN_NT)
            ((float4*)wsm)[i] = wsrc[i];
        __syncthreads();
        #pragma unroll 4
        for (int k = 0; k < SN_KC; k++) {
            float4 w4 = *(const float4*)(wsm + k * NJP + jg * 4);
            float4 z4 = *(const float4*)(zsT + (kc + k) * SN_ZS + bg * 4);
            float2 z01 = make_float2(z4.x, z4.y);
            float2 z23 = make_float2(z4.z, z4.w);
            acc[0][0] = ffma2(z01, make_float2(w4.x, w4.x), acc[0][0]);
            acc[0][1] = ffma2(z23, make_float2(w4.x, w4.x), acc[0][1]);
            acc[1][0] = ffma2(z01, make_float2(w4.y, w4.y), acc[1][0]);
            acc[1][1] = ffma2(z23, make_float2(w4.y, w4.y), acc[1][1]);
            acc[2][0] = ffma2(z01, make_float2(w4.z, w4.z), acc[2][0]);
            acc[2][1] = ffma2(z23, make_float2(w4.z, w4.z), acc[2][1]);
            acc[3][0] = ffma2(z01, make_float2(w4.w, w4.w), acc[3][0]);
            acc[3][1] = ffma2(z23, make_float2(w4.w, w4.w), acc[3][1]);
        }
    }
    #pragma unroll
    for (int jj = 0; jj < 4; jj++) {
        int j = jg * 4 + jj;
        if (j < NIq) {
            int b = b0 + bg * 4;
            g_W[ b      * NIq + j] = acc[jj][0].x;
            g_W[(b + 1) * NIq + j] = acc[jj][0].y;
            g_W[(b + 2) * NIq + j] = acc[jj][1].x;
            g_W[(b + 3) * NIq + j] = acc[jj][1].y;
        }
    }
}

// ---------------------------------------------------------------------------
// K3: combine. Phase 1 identical to the 68.3 best (MLP-6 fp16 gathers).
// Phase 2: float2 items — 320 work items (>256 threads stay busy), 19
// LDS.64 per item: HALF the phase-2 LDS instruction count of the scalar
// version without R14's thread-idling.
// ---------------------------------------------------------------------------
#define BPB 2
#define P1_ITEMS (BPB * NIq * 2)     // 760
#define P2_ITEMS (BPB * Fq * 8)      // 320 float2 outputs
__global__ __launch_bounds__(256) void k_combine(
    const int* __restrict__ hash_idx,    // (2, B, NI)
    const int* __restrict__ inter,       // (20, 19)
    float*     __restrict__ out)         // (B, 20, 16)
{
    __shared__ float ws[BPB * NIq];
    __shared__ __align__(16) float embw[BPB][NIq * 20];
    __shared__ int idxs[Fq * (Fq - 1)];
    __shared__ int hs0[BPB * NIq];
    __shared__ int hs1[BPB * NIq];

    const int b0  = blockIdx.x * BPB;
    const int tid = threadIdx.x;

    for (int i = tid; i < BPB * NIq; i += 256) {
        int bb = i / NIq, j = i - bb * NIq;
        ws[i]  = g_W[(b0 + bb) * NIq + j];
        hs0[i] = hash_idx[(b0 + bb) * NIq + j];
        hs1[i] = hash_idx[Bq * NIq + (b0 + bb) * NIq + j];
    }
    for (int i = tid; i < Fq * (Fq - 1); i += 256) idxs[i] = inter[i];
    __syncthreads();

    // phase 1: 3 slots/thread, all 6 gathers issued before any convert
    uint4 av[3], cv[3];
    float wv[3];
    int jjv[3], qv[3];
    bool val[3];
    #pragma unroll
    for (int s = 0; s < 3; s++) {
        int t = tid + s * 256;
        val[s] = (t < P1_ITEMS);
        if (val[s]) {
            int jj = t >> 1, q = t & 1;
            jjv[s] = jj; qv[s] = q;
            av[s] = *(const uint4*)(g_CT0h + hs0[jj] * Dq + q * 8);
            cv[s] = *(const uint4*)(g_CT1h + hs1[jj] * Dq + q * 8);
            wv[s] = ws[jj];
        }
    }
    #pragma unroll
    for (int s = 0; s < 3; s++) {
        if (!val[s]) continue;
        float w = wv[s];
        float2 fa, fc;
        float o[8];
        fa = __half22float2(*(__half2*)&av[s].x); fc = __half22float2(*(__half2*)&cv[s].x);
        o[0] = (fa.x + fc.x) * w; o[1] = (fa.y + fc.y) * w;
        fa = __half22float2(*(__half2*)&av[s].y); fc = __half22float2(*(__half2*)&cv[s].y);
        o[2] = (fa.x + fc.x) * w; o[3] = (fa.y + fc.y) * w;
        fa = __half22float2(*(__half2*)&av[s].z); fc = __half22float2(*(__half2*)&cv[s].z);
        o[4] = (fa.x + fc.x) * w; o[5] = (fa.y + fc.y) * w;
        fa = __half22float2(*(__half2*)&av[s].w); fc = __half22float2(*(__half2*)&cv[s].w);
        o[6] = (fa.x + fc.x) * w; o[7] = (fa.y + fc.y) * w;
        int bb = jjv[s] / NIq, j = jjv[s] - bb * NIq;
        float* dst = &embw[bb][j * 20 + qv[s] * 8];
        *(float4*)dst       = make_float4(o[0], o[1], o[2], o[3]);
        *(float4*)(dst + 4) = make_float4(o[4], o[5], o[6], o[7]);
    }
    __syncthreads();

    // phase 2: one float2 output per item; 19 LDS.64 + 1 STG.64
    for (int t = tid; t < P2_ITEMS; t += 256) {
        int q  = t & 7;                 // float2 slot within the 16 d's
        int f  = (t >> 3) % Fq;
        int bb = t / (Fq * 8);
        const int* row = idxs + f * (Fq - 1);
        float2 s = make_float2(0.f, 0.f);
        #pragma unroll
        for (int p = 0; p < Fq - 1; p++) {
            float2 v = *(const float2*)(&embw[bb][row[p] * 20 + q * 2]);
            s.x += v.x; s.y += v.y;
        }
        *(float2*)(out + (b0 + bb) * Fq * Dq + f * Dq + q * 2) = s;
    }
}

// ---------------------------------------------------------------------------
extern "C" void kernel_launch(void* const* d_in, const int* in_sizes, int n_in,
                              void* d_out, int out_size) {
    const float* origin   = (const float*)d_in[0];  // (B, F, D)
    const float* codebook = (const float*)d_in[1];  // (NB, D)
    const float* Wt       = (const float*)d_in[2];  // (32, 16)
    const float* w1       = (const float*)d_in[3];  // (320, 320)
    const float* w2       = (const float*)d_in[4];  // (320, 190)
    const int*   hash     = (const int*)d_in[5];    // (2, B, NI)
    const int*   inter    = (const int*)d_in[6];    // (20, 19)
    float*       out      = (float*)d_out;

    k_pre<<<W12_TILES + CT_BLOCKS, 256>>>(w1, w2, Wt, codebook);
    k_senet<<<Bq / SN_TB, SN_NT>>>(origin);
    k_combine<<<Bq / BPB, 256>>>(hash, inter, out);
}